// round 14
// baseline (speedup 1.0000x reference)
#include <cuda_runtime.h>
#include <cuda_fp16.h>
#include <cstdint>
#include <cstddef>

#define U   256
#define INP 64
#define TT  128
#define BB  256
#define UNFOLDS 6
#define EPSV 1e-8f
#define NTHR 256          // 4 batch-pairs x 64 j-columns
#define CLU  4
#define JPC  64
#define BPC  8

// smem layout offsets (bytes)
#define OFF_RECA   0                       // float4[128*64] (s2e,s2o,ce,co) = 131072
#define OFF_RECAN  131072                  // float2[128*64] (ane,ano)       = 65536
#define OFF_VBUF   196608                  // f32 [2][8][256]                = 16384
#define OFF_XS     212992                  // f32 [2][8][64]                 = 4096
#define OFF_TSS    217088                  // f32 [2][8]                     = 64
#define OFF_RED    217152                  // f32 [8][64]                    = 2048
#define OFF_PART   219200                  // f32 [4][8]                     = 128
#define SMEM_BYTES 219328

// packed params in device globals (prep output), all fp32
__device__ float4 g_rpA [(U/2) * U];       // (s2 even, s2 odd, c even, c odd)
__device__ float2 g_rAnF[(U/2) * U];       // (an even, an odd)
__device__ float4 g_spA [(INP/2) * U];     // sensory: global/L2-resident
__device__ float2 g_sAnF[(INP/2) * U];
__device__ float g_CnR[U], g_CdR[U], g_CnS[U], g_CdS[U];

__device__ __forceinline__ float tanh_ap(float x) {
    float r;
    asm("tanh.approx.f32 %0, %1;" : "=f"(r) : "f"(x));
    return r;
}
__device__ __forceinline__ uint32_t smem_u32(const void* p) {
    uint32_t a;
    asm("{ .reg .u64 t; cvta.to.shared.u64 t, %1; cvt.u32.u64 %0, t; }" : "=r"(a) : "l"(p));
    return a;
}
__device__ __forceinline__ uint32_t mapa_rank(uint32_t a, uint32_t r) {
    uint32_t o;
    asm("mapa.shared::cluster.u32 %0, %1, %2;" : "=r"(o) : "r"(a), "r"(r));
    return o;
}
__device__ __forceinline__ void st_cluster_f32(uint32_t a, float v) {
    asm volatile("st.shared::cluster.f32 [%0], %1;" :: "r"(a), "f"(v) : "memory");
}

// ---------------- fused prep kernel ----------------
__global__ void prep_all(const float* __restrict__ mu,  const float* __restrict__ sg,
                         const float* __restrict__ w,   const float* __restrict__ er,
                         const float* __restrict__ smu, const float* __restrict__ ssg,
                         const float* __restrict__ sw,  const float* __restrict__ ser,
                         const float* __restrict__ iw,  const float* __restrict__ ib) {
    int j = blockIdx.x;
    int i = threadIdx.x;
    __shared__ float rn[256], rd[256], sn[64], sd[64];

    {
        int idx = i * U + j;
        float s2 = 0.5f * sg[idx];
        float c  = -s2 * mu[idx];
        float a  = 0.5f * w[idx];
        float an = a * er[idx];
        int i2 = i >> 1, lo = i & 1;
        float* pa = (float*)&g_rpA[i2 * U + j];
        pa[lo]     = s2;
        pa[2 + lo] = c;
        ((float*)&g_rAnF[i2 * U + j])[lo] = an;
        rn[i] = an;
        rd[i] = a;
    }
    if (i < INP) {
        int idx = i * U + j;
        float hs = 0.5f * ssg[idx];
        float s2 = hs * iw[i];
        float c  = hs * (ib[i] - smu[idx]);
        float a  = 0.5f * sw[idx];
        float an = a * ser[idx];
        int i2 = i >> 1, lo = i & 1;
        float* pa = (float*)&g_spA[i2 * U + j];
        pa[lo]     = s2;
        pa[2 + lo] = c;
        ((float*)&g_sAnF[i2 * U + j])[lo] = an;
        sn[i] = an;
        sd[i] = a;
    }
    __syncthreads();
    #pragma unroll
    for (int s = 128; s > 0; s >>= 1) {
        if (i < s) { rn[i] += rn[i + s]; rd[i] += rd[i + s]; }
        if (s <= 32 && i < s) { sn[i] += sn[i + s]; sd[i] += sd[i + s]; }
        __syncthreads();
    }
    if (i == 0) {
        g_CnR[j] = rn[0]; g_CdR[j] = rd[0];
        g_CnS[j] = sn[0]; g_CdS[j] = sd[0];
    }
}

// ---------------- main recurrence kernel ----------------
// 4-CTA cluster covers 8 batches; CTA rank r owns j in [r*64, r*64+64).
__global__ void __launch_bounds__(NTHR, 1) __cluster_dims__(CLU, 1, 1)
ltc_main(const float* __restrict__ x, const float* __restrict__ ts,
         const float* __restrict__ gleak, const float* __restrict__ vleak,
         const float* __restrict__ cm,
         const float* __restrict__ ow, const float* __restrict__ ob,
         const float* __restrict__ hw, const float* __restrict__ hb,
         float* __restrict__ out)
{
    extern __shared__ char dsm[];
    float4* recA  = (float4*)(dsm + OFF_RECA);
    float2* recAn = (float2*)(dsm + OFF_RECAN);
    float*  vbuf  = (float*)(dsm + OFF_VBUF);
    float*  xs    = (float*)(dsm + OFF_XS);
    float*  tss   = (float*)(dsm + OFF_TSS);
    float*  red   = (float*)(dsm + OFF_RED);
    float*  part  = (float*)(dsm + OFF_PART);

    int tid = threadIdx.x;
    uint32_t rank;
    asm("mov.u32 %0, %%cluster_ctarank;" : "=r"(rank));

    // ---- stage recurrent parameters for this CTA's 64 columns ----
    for (int idx = tid; idx < 128 * JPC; idx += NTHR) {
        int i2 = idx >> 6;
        int j  = (int)rank * JPC + (idx & 63);
        recA[idx]  = g_rpA[i2 * U + j];
        recAn[idx] = g_rAnF[i2 * U + j];
    }
    for (int idx = tid; idx < 2 * BPC * 256; idx += NTHR) vbuf[idx] = 0.f;
    __syncthreads();

    int bp = tid >> 6;            // batch-pair 0..3
    int jl = tid & 63;
    int jg = (int)rank * JPC + jl;
    int bg = blockIdx.x >> 2;     // cluster id (32 clusters)
    float cmj  = cm[jg];
    float gl   = gleak[jg];
    float glvl = gl * vleak[jg];
    float CnR = g_CnR[jg], CdR = g_CdR[jg];
    float CnS = g_CnS[jg], CdS = g_CdS[jg];

    const float4* sA  = g_spA  + jg;   // sensory params from global/L2
    const float2* sAn = g_sAnF + jg;

    uint32_t vloc = smem_u32(vbuf);
    uint32_t vpeer[CLU];
    #pragma unroll
    for (int r = 0; r < CLU; r++) vpeer[r] = mapa_rank(vloc, (uint32_t)r);

    // stage inputs + timespans for timestep t into buffer nb
    auto do_stage = [&](int nb, int t) {
        #pragma unroll
        for (int k = 0; k < 2; k++) {
            int idx = tid + k * NTHR;
            int bsx = idx >> 6, ii = idx & 63;
            xs[nb * 512 + idx] = x[((size_t)(bg * BPC + bsx)) * TT * INP + t * INP + ii];
        }
        if (tid < BPC) tss[nb * 8 + tid] = ts[(size_t)(bg * BPC + tid) * TT + t];
    };
    // sensory sums for buffer nb (fp32, params streamed from L2)
    auto do_sensory = [&](int nb, float& o_cmt0, float& o_cmt1,
                          float& o_bN0, float& o_bD0, float& o_bN1, float& o_bD1) {
        float c0 = __fdividef(6.0f * cmj, tss[nb * 8 + bp * 2]);
        float c1 = __fdividef(6.0f * cmj, tss[nb * 8 + bp * 2 + 1]);
        float sN0 = CnS, sD0 = CdS, sN1 = CnS, sD1 = CdS;
        const float* x0 = xs + nb * 512 + (bp * 2) * 64;
        const float* x1 = x0 + 64;
        #pragma unroll 8
        for (int i2 = 0; i2 < 32; i2++) {
            float4 pa = sA [i2 * U];
            float2 an = sAn[i2 * U];
            float2 xa = *(const float2*)(x0 + 2 * i2);
            float2 xb = *(const float2*)(x1 + 2 * i2);
            float t00 = tanh_ap(fmaf(pa.x, xa.x, pa.z));
            float t01 = tanh_ap(fmaf(pa.y, xa.y, pa.w));
            float t10 = tanh_ap(fmaf(pa.x, xb.x, pa.z));
            float t11 = tanh_ap(fmaf(pa.y, xb.y, pa.w));
            float ax = fabsf(an.x), ay = fabsf(an.y);
            sN0 = fmaf(an.x, t00, sN0); sD0 = fmaf(ax, t00, sD0);
            sN0 = fmaf(an.y, t01, sN0); sD0 = fmaf(ay, t01, sD0);
            sN1 = fmaf(an.x, t10, sN1); sD1 = fmaf(ax, t10, sD1);
            sN1 = fmaf(an.y, t11, sN1); sD1 = fmaf(ay, t11, sD1);
        }
        o_cmt0 = c0; o_cmt1 = c1;
        o_bN0 = glvl + CnR + sN0; o_bD0 = c0 + gl + CdR + sD0 + EPSV;
        o_bN1 = glvl + CnR + sN1; o_bD1 = c1 + gl + CdR + sD1 + EPSV;
    };

    // prologue: t=0 staging + sensory (CTA-local work)
    do_stage(0, 0);
    __syncthreads();
    float cmt0, cmt1, bN0, bD0, bN1, bD1;
    do_sensory(0, cmt0, cmt1, bN0, bD0, bN1, bD1);
    float ncmt0, ncmt1, nbN0, nbD0, nbN1, nbD1;

    float v0 = 0.f, v1 = 0.f;
    int p = 0, nb = 0;

    // all CTAs: vbuf zeroed + params staged before first publish
    asm volatile("barrier.cluster.arrive.aligned;" ::: "memory");
    asm volatile("barrier.cluster.wait.aligned;"   ::: "memory");

    for (int t = 0; t < TT; t++) {
        for (int u = 0; u < UNFOLDS; u++) {
            float aN0 = 0.f, aD0 = 0.f, aN1 = 0.f, aD1 = 0.f;
            const float* vr0 = vbuf + (p * BPC + bp * 2) * 256;
            const float* vr1 = vr0 + 256;
            #pragma unroll 4
            for (int i4 = 0; i4 < 64; i4++) {
                float4 va4 = *(const float4*)(vr0 + 4 * i4);
                float4 vb4 = *(const float4*)(vr1 + 4 * i4);
                #pragma unroll
                for (int k = 0; k < 2; k++) {
                    int i2 = 2 * i4 + k;
                    float4 pa = recA[i2 * JPC + jl];
                    float2 an = recAn[i2 * JPC + jl];
                    float vax = k ? va4.z : va4.x;
                    float vay = k ? va4.w : va4.y;
                    float vbx = k ? vb4.z : vb4.x;
                    float vby = k ? vb4.w : vb4.y;
                    float t00 = tanh_ap(fmaf(pa.x, vax, pa.z));
                    float t01 = tanh_ap(fmaf(pa.y, vay, pa.w));
                    float t10 = tanh_ap(fmaf(pa.x, vbx, pa.z));
                    float t11 = tanh_ap(fmaf(pa.y, vby, pa.w));
                    float ax = fabsf(an.x), ay = fabsf(an.y);
                    aN0 = fmaf(an.x, t00, aN0); aD0 = fmaf(ax, t00, aD0);
                    aN0 = fmaf(an.y, t01, aN0); aD0 = fmaf(ay, t01, aD0);
                    aN1 = fmaf(an.x, t10, aN1); aD1 = fmaf(ax, t10, aD1);
                    aN1 = fmaf(an.y, t11, aN1); aD1 = fmaf(ay, t11, aD1);
                }
            }
            v0 = __fdividef(fmaf(cmt0, v0, bN0 + aN0), bD0 + aD0);
            v1 = __fdividef(fmaf(cmt1, v1, bN1 + aN1), bD1 + aD1);

            // publish new fp32 v to all 4 CTAs (buffer p^1)
            uint32_t off = ((uint32_t)((p ^ 1) * BPC + bp * 2) * 256 + (uint32_t)jg) * 4;
            #pragma unroll
            for (int r = 0; r < CLU; r++) {
                st_cluster_f32(vpeer[r] + off, v0);
                st_cluster_f32(vpeer[r] + off + 1024, v1);
            }
            asm volatile("barrier.cluster.arrive.aligned;" ::: "memory");
            // hide next timestep's staging + sensory behind the barrier wait
            if (u == UNFOLDS - 1 && t + 1 < TT) {
                do_stage(nb ^ 1, t + 1);
                __syncthreads();
                do_sensory(nb ^ 1, ncmt0, ncmt1, nbN0, nbD0, nbN1, nbD1);
            }
            asm volatile("barrier.cluster.wait.aligned;" ::: "memory");
            p ^= 1;
        }
        if (t + 1 < TT) {
            cmt0 = ncmt0; cmt1 = ncmt1;
            bN0 = nbN0; bD0 = nbD0; bN1 = nbN1; bD1 = nbD1;
            nb ^= 1;
        }
    }

    // ---- head: out[b] = sum_j (v*ow + ob)*hw + hb ----
    int r0 = bp * 2, r1 = r0 + 1;
    red[r0 * JPC + jl] = fmaf(v0, ow[jg], ob[jg]) * hw[jg];
    red[r1 * JPC + jl] = fmaf(v1, ow[jg], ob[jg]) * hw[jg];
    __syncthreads();
    #pragma unroll
    for (int s = 32; s > 0; s >>= 1) {
        if (jl < s) {
            red[r0 * JPC + jl] += red[r0 * JPC + jl + s];
            red[r1 * JPC + jl] += red[r1 * JPC + jl + s];
        }
        __syncthreads();
    }
    if (jl == 0) {
        uint32_t pa = mapa_rank(smem_u32(part), 0);
        st_cluster_f32(pa + (rank * BPC + (uint32_t)r0) * 4, red[r0 * JPC]);
        st_cluster_f32(pa + (rank * BPC + (uint32_t)r1) * 4, red[r1 * JPC]);
    }
    asm volatile("barrier.cluster.arrive.aligned;" ::: "memory");
    asm volatile("barrier.cluster.wait.aligned;"   ::: "memory");
    if (rank == 0 && tid < BPC) {
        float s = hb[0];
        #pragma unroll
        for (int r = 0; r < CLU; r++) s += part[r * BPC + tid];
        out[bg * BPC + tid] = s;
    }
}

// ---------------- launch ----------------
extern "C" void kernel_launch(void* const* d_in, const int* in_sizes, int n_in,
                              void* d_out, int out_size) {
    const float* x     = (const float*)d_in[0];
    const float* ts    = (const float*)d_in[1];
    const float* smu   = (const float*)d_in[2];
    const float* ssg   = (const float*)d_in[3];
    const float* sw    = (const float*)d_in[4];
    const float* ser   = (const float*)d_in[5];
    const float* mu    = (const float*)d_in[6];
    const float* sg    = (const float*)d_in[7];
    const float* w     = (const float*)d_in[8];
    const float* er    = (const float*)d_in[9];
    const float* gleak = (const float*)d_in[10];
    const float* vleak = (const float*)d_in[11];
    const float* cm    = (const float*)d_in[12];
    const float* iw    = (const float*)d_in[13];
    const float* ib    = (const float*)d_in[14];
    const float* ow    = (const float*)d_in[15];
    const float* ob    = (const float*)d_in[16];
    const float* hw    = (const float*)d_in[17];
    const float* hb    = (const float*)d_in[18];
    float* out = (float*)d_out;

    cudaFuncSetAttribute(ltc_main, cudaFuncAttributeMaxDynamicSharedMemorySize, SMEM_BYTES);

    prep_all<<<U, 256>>>(mu, sg, w, er, smu, ssg, sw, ser, iw, ib);
    // 256 batches / 8 per cluster = 32 clusters = 128 CTAs
    ltc_main<<<BB / BPC * CLU, NTHR, SMEM_BYTES>>>(x, ts, gleak, vleak, cm,
                                                   ow, ob, hw, hb, out);
}

// round 15
// speedup vs baseline: 1.0029x; 1.0029x over previous
#include <cuda_runtime.h>
#include <cuda_fp16.h>
#include <cstdint>
#include <cstddef>

#define U   256
#define INP 64
#define TT  128
#define BB  256
#define UNFOLDS 6
#define EPSV 1e-8f
#define NTHR 256          // 4 batch-pairs x 64 j-columns
#define CLU  4
#define JPC  64
#define BPC  8

// smem layout offsets (bytes)
#define OFF_RECA   0                       // float4[128*64] (s2e,s2o,ce,co) = 131072
#define OFF_RECAN  131072                  // float2[128*64] (ane,ano)       = 65536
#define OFF_VBUF   196608                  // f32 [2][8][256]                = 16384
#define OFF_XS     212992                  // f32 [2][8][64]                 = 4096
#define OFF_TSS    217088                  // f32 [2][8]                     = 64
#define OFF_RED    217152                  // f32 [8][64]                    = 2048
#define OFF_PART   219200                  // f32 [4][8]                     = 128
#define SMEM_BYTES 219328

// packed params in device globals (prep output), all fp32
__device__ float4 g_rpA [(U/2) * U];       // (s2 even, s2 odd, c even, c odd)
__device__ float2 g_rAnF[(U/2) * U];       // (an even, an odd)
__device__ float4 g_spA [(INP/2) * U];     // sensory: global/L2-resident
__device__ float2 g_sAnF[(INP/2) * U];
__device__ float g_CnR[U], g_CdR[U], g_CnS[U], g_CdS[U];

__device__ __forceinline__ float tanh_ap(float x) {
    float r;
    asm("tanh.approx.f32 %0, %1;" : "=f"(r) : "f"(x));
    return r;
}
__device__ __forceinline__ uint32_t smem_u32(const void* p) {
    uint32_t a;
    asm("{ .reg .u64 t; cvta.to.shared.u64 t, %1; cvt.u32.u64 %0, t; }" : "=r"(a) : "l"(p));
    return a;
}
__device__ __forceinline__ uint32_t mapa_rank(uint32_t a, uint32_t r) {
    uint32_t o;
    asm("mapa.shared::cluster.u32 %0, %1, %2;" : "=r"(o) : "r"(a), "r"(r));
    return o;
}
__device__ __forceinline__ void st_cluster_f32(uint32_t a, float v) {
    asm volatile("st.shared::cluster.f32 [%0], %1;" :: "r"(a), "f"(v) : "memory");
}

// ---------------- fused prep kernel ----------------
__global__ void prep_all(const float* __restrict__ mu,  const float* __restrict__ sg,
                         const float* __restrict__ w,   const float* __restrict__ er,
                         const float* __restrict__ smu, const float* __restrict__ ssg,
                         const float* __restrict__ sw,  const float* __restrict__ ser,
                         const float* __restrict__ iw,  const float* __restrict__ ib) {
    int j = blockIdx.x;
    int i = threadIdx.x;
    __shared__ float rn[256], rd[256], sn[64], sd[64];

    {
        int idx = i * U + j;
        float s2 = 0.5f * sg[idx];
        float c  = -s2 * mu[idx];
        float a  = 0.5f * w[idx];
        float an = a * er[idx];
        int i2 = i >> 1, lo = i & 1;
        float* pa = (float*)&g_rpA[i2 * U + j];
        pa[lo]     = s2;
        pa[2 + lo] = c;
        ((float*)&g_rAnF[i2 * U + j])[lo] = an;
        rn[i] = an;
        rd[i] = a;
    }
    if (i < INP) {
        int idx = i * U + j;
        float hs = 0.5f * ssg[idx];
        float s2 = hs * iw[i];
        float c  = hs * (ib[i] - smu[idx]);
        float a  = 0.5f * sw[idx];
        float an = a * ser[idx];
        int i2 = i >> 1, lo = i & 1;
        float* pa = (float*)&g_spA[i2 * U + j];
        pa[lo]     = s2;
        pa[2 + lo] = c;
        ((float*)&g_sAnF[i2 * U + j])[lo] = an;
        sn[i] = an;
        sd[i] = a;
    }
    __syncthreads();
    #pragma unroll
    for (int s = 128; s > 0; s >>= 1) {
        if (i < s) { rn[i] += rn[i + s]; rd[i] += rd[i + s]; }
        if (s <= 32 && i < s) { sn[i] += sn[i + s]; sd[i] += sd[i + s]; }
        __syncthreads();
    }
    if (i == 0) {
        g_CnR[j] = rn[0]; g_CdR[j] = rd[0];
        g_CnS[j] = sn[0]; g_CdS[j] = sd[0];
    }
}

// ---------------- main recurrence kernel ----------------
// 4-CTA cluster covers 8 batches; CTA rank r owns j in [r*64, r*64+64).
__global__ void __launch_bounds__(NTHR, 1) __cluster_dims__(CLU, 1, 1)
ltc_main(const float* __restrict__ x, const float* __restrict__ ts,
         const float* __restrict__ gleak, const float* __restrict__ vleak,
         const float* __restrict__ cm,
         const float* __restrict__ ow, const float* __restrict__ ob,
         const float* __restrict__ hw, const float* __restrict__ hb,
         float* __restrict__ out)
{
    extern __shared__ char dsm[];
    float4* recA  = (float4*)(dsm + OFF_RECA);
    float2* recAn = (float2*)(dsm + OFF_RECAN);
    float*  vbuf  = (float*)(dsm + OFF_VBUF);
    float*  xs    = (float*)(dsm + OFF_XS);
    float*  tss   = (float*)(dsm + OFF_TSS);
    float*  red   = (float*)(dsm + OFF_RED);
    float*  part  = (float*)(dsm + OFF_PART);

    int tid = threadIdx.x;
    uint32_t rank;
    asm("mov.u32 %0, %%cluster_ctarank;" : "=r"(rank));

    // ---- stage recurrent parameters for this CTA's 64 columns ----
    for (int idx = tid; idx < 128 * JPC; idx += NTHR) {
        int i2 = idx >> 6;
        int j  = (int)rank * JPC + (idx & 63);
        recA[idx]  = g_rpA[i2 * U + j];
        recAn[idx] = g_rAnF[i2 * U + j];
    }
    for (int idx = tid; idx < 2 * BPC * 256; idx += NTHR) vbuf[idx] = 0.f;
    __syncthreads();

    int bp = tid >> 6;            // batch-pair 0..3
    int jl = tid & 63;
    int jg = (int)rank * JPC + jl;
    int bg = blockIdx.x >> 2;     // cluster id (32 clusters)
    float cmj  = cm[jg];
    float gl   = gleak[jg];
    float glvl = gl * vleak[jg];
    float CnR = g_CnR[jg], CdR = g_CdR[jg];
    float CnS = g_CnS[jg], CdS = g_CdS[jg];

    const float4* sA  = g_spA  + jg;   // sensory params from global/L2
    const float2* sAn = g_sAnF + jg;

    uint32_t vloc = smem_u32(vbuf);
    uint32_t vpeer[CLU];
    #pragma unroll
    for (int r = 0; r < CLU; r++) vpeer[r] = mapa_rank(vloc, (uint32_t)r);

    // stage inputs + timespans for timestep t into buffer nb
    auto do_stage = [&](int nb, int t) {
        #pragma unroll
        for (int k = 0; k < 2; k++) {
            int idx = tid + k * NTHR;
            int bsx = idx >> 6, ii = idx & 63;
            xs[nb * 512 + idx] = x[((size_t)(bg * BPC + bsx)) * TT * INP + t * INP + ii];
        }
        if (tid < BPC) tss[nb * 8 + tid] = ts[(size_t)(bg * BPC + tid) * TT + t];
    };
    // sensory sums for buffer nb (fp32, params streamed from L2)
    auto do_sensory = [&](int nb, float& o_cmt0, float& o_cmt1,
                          float& o_bN0, float& o_bD0, float& o_bN1, float& o_bD1) {
        float c0 = __fdividef(6.0f * cmj, tss[nb * 8 + bp * 2]);
        float c1 = __fdividef(6.0f * cmj, tss[nb * 8 + bp * 2 + 1]);
        float sN0 = CnS, sD0 = CdS, sN1 = CnS, sD1 = CdS;
        const float* x0 = xs + nb * 512 + (bp * 2) * 64;
        const float* x1 = x0 + 64;
        #pragma unroll 8
        for (int i2 = 0; i2 < 32; i2++) {
            float4 pa = sA [i2 * U];
            float2 an = sAn[i2 * U];
            float2 xa = *(const float2*)(x0 + 2 * i2);
            float2 xb = *(const float2*)(x1 + 2 * i2);
            float t00 = tanh_ap(fmaf(pa.x, xa.x, pa.z));
            float t01 = tanh_ap(fmaf(pa.y, xa.y, pa.w));
            float t10 = tanh_ap(fmaf(pa.x, xb.x, pa.z));
            float t11 = tanh_ap(fmaf(pa.y, xb.y, pa.w));
            float ax = fabsf(an.x), ay = fabsf(an.y);
            sN0 = fmaf(an.x, t00, sN0); sD0 = fmaf(ax, t00, sD0);
            sN0 = fmaf(an.y, t01, sN0); sD0 = fmaf(ay, t01, sD0);
            sN1 = fmaf(an.x, t10, sN1); sD1 = fmaf(ax, t10, sD1);
            sN1 = fmaf(an.y, t11, sN1); sD1 = fmaf(ay, t11, sD1);
        }
        o_cmt0 = c0; o_cmt1 = c1;
        o_bN0 = glvl + CnR + sN0; o_bD0 = c0 + gl + CdR + sD0 + EPSV;
        o_bN1 = glvl + CnR + sN1; o_bD1 = c1 + gl + CdR + sD1 + EPSV;
    };

    // prologue: t=0 staging + sensory (CTA-local work)
    do_stage(0, 0);
    __syncthreads();
    float cmt0, cmt1, bN0, bD0, bN1, bD1;
    do_sensory(0, cmt0, cmt1, bN0, bD0, bN1, bD1);
    float ncmt0, ncmt1, nbN0, nbD0, nbN1, nbD1;

    float v0 = 0.f, v1 = 0.f;
    int p = 0, nb = 0;

    // all CTAs: vbuf zeroed + params staged before first publish
    asm volatile("barrier.cluster.arrive.aligned;" ::: "memory");
    asm volatile("barrier.cluster.wait.aligned;"   ::: "memory");

    for (int t = 0; t < TT; t++) {
        for (int u = 0; u < UNFOLDS; u++) {
            float aN0 = 0.f, aD0 = 0.f, aN1 = 0.f, aD1 = 0.f;
            const float* vr0 = vbuf + (p * BPC + bp * 2) * 256;
            const float* vr1 = vr0 + 256;
            #pragma unroll 4
            for (int i4 = 0; i4 < 64; i4++) {
                float4 va4 = *(const float4*)(vr0 + 4 * i4);
                float4 vb4 = *(const float4*)(vr1 + 4 * i4);
                #pragma unroll
                for (int k = 0; k < 2; k++) {
                    int i2 = 2 * i4 + k;
                    float4 pa = recA[i2 * JPC + jl];
                    float2 an = recAn[i2 * JPC + jl];
                    float vax = k ? va4.z : va4.x;
                    float vay = k ? va4.w : va4.y;
                    float vbx = k ? vb4.z : vb4.x;
                    float vby = k ? vb4.w : vb4.y;
                    float t00 = tanh_ap(fmaf(pa.x, vax, pa.z));
                    float t01 = tanh_ap(fmaf(pa.y, vay, pa.w));
                    float t10 = tanh_ap(fmaf(pa.x, vbx, pa.z));
                    float t11 = tanh_ap(fmaf(pa.y, vby, pa.w));
                    float ax = fabsf(an.x), ay = fabsf(an.y);
                    aN0 = fmaf(an.x, t00, aN0); aD0 = fmaf(ax, t00, aD0);
                    aN0 = fmaf(an.y, t01, aN0); aD0 = fmaf(ay, t01, aD0);
                    aN1 = fmaf(an.x, t10, aN1); aD1 = fmaf(ax, t10, aD1);
                    aN1 = fmaf(an.y, t11, aN1); aD1 = fmaf(ay, t11, aD1);
                }
            }
            v0 = __fdividef(fmaf(cmt0, v0, bN0 + aN0), bD0 + aD0);
            v1 = __fdividef(fmaf(cmt1, v1, bN1 + aN1), bD1 + aD1);

            // publish new fp32 v to all 4 CTAs (buffer p^1)
            uint32_t off = ((uint32_t)((p ^ 1) * BPC + bp * 2) * 256 + (uint32_t)jg) * 4;
            #pragma unroll
            for (int r = 0; r < CLU; r++) {
                st_cluster_f32(vpeer[r] + off, v0);
                st_cluster_f32(vpeer[r] + off + 1024, v1);
            }
            asm volatile("barrier.cluster.arrive.aligned;" ::: "memory");
            // hide next timestep's staging + sensory behind the barrier wait
            if (u == UNFOLDS - 1 && t + 1 < TT) {
                do_stage(nb ^ 1, t + 1);
                __syncthreads();
                do_sensory(nb ^ 1, ncmt0, ncmt1, nbN0, nbD0, nbN1, nbD1);
            }
            asm volatile("barrier.cluster.wait.aligned;" ::: "memory");
            p ^= 1;
        }
        if (t + 1 < TT) {
            cmt0 = ncmt0; cmt1 = ncmt1;
            bN0 = nbN0; bD0 = nbD0; bN1 = nbN1; bD1 = nbD1;
            nb ^= 1;
        }
    }

    // ---- head: out[b] = sum_j (v*ow + ob)*hw + hb ----
    int r0 = bp * 2, r1 = r0 + 1;
    red[r0 * JPC + jl] = fmaf(v0, ow[jg], ob[jg]) * hw[jg];
    red[r1 * JPC + jl] = fmaf(v1, ow[jg], ob[jg]) * hw[jg];
    __syncthreads();
    #pragma unroll
    for (int s = 32; s > 0; s >>= 1) {
        if (jl < s) {
            red[r0 * JPC + jl] += red[r0 * JPC + jl + s];
            red[r1 * JPC + jl] += red[r1 * JPC + jl + s];
        }
        __syncthreads();
    }
    if (jl == 0) {
        uint32_t pa = mapa_rank(smem_u32(part), 0);
        st_cluster_f32(pa + (rank * BPC + (uint32_t)r0) * 4, red[r0 * JPC]);
        st_cluster_f32(pa + (rank * BPC + (uint32_t)r1) * 4, red[r1 * JPC]);
    }
    asm volatile("barrier.cluster.arrive.aligned;" ::: "memory");
    asm volatile("barrier.cluster.wait.aligned;"   ::: "memory");
    if (rank == 0 && tid < BPC) {
        float s = hb[0];
        #pragma unroll
        for (int r = 0; r < CLU; r++) s += part[r * BPC + tid];
        out[bg * BPC + tid] = s;
    }
}

// ---------------- launch ----------------
extern "C" void kernel_launch(void* const* d_in, const int* in_sizes, int n_in,
                              void* d_out, int out_size) {
    const float* x     = (const float*)d_in[0];
    const float* ts    = (const float*)d_in[1];
    const float* smu   = (const float*)d_in[2];
    const float* ssg   = (const float*)d_in[3];
    const float* sw    = (const float*)d_in[4];
    const float* ser   = (const float*)d_in[5];
    const float* mu    = (const float*)d_in[6];
    const float* sg    = (const float*)d_in[7];
    const float* w     = (const float*)d_in[8];
    const float* er    = (const float*)d_in[9];
    const float* gleak = (const float*)d_in[10];
    const float* vleak = (const float*)d_in[11];
    const float* cm    = (const float*)d_in[12];
    const float* iw    = (const float*)d_in[13];
    const float* ib    = (const float*)d_in[14];
    const float* ow    = (const float*)d_in[15];
    const float* ob    = (const float*)d_in[16];
    const float* hw    = (const float*)d_in[17];
    const float* hb    = (const float*)d_in[18];
    float* out = (float*)d_out;

    cudaFuncSetAttribute(ltc_main, cudaFuncAttributeMaxDynamicSharedMemorySize, SMEM_BYTES);

    prep_all<<<U, 256>>>(mu, sg, w, er, smu, ssg, sw, ser, iw, ib);
    // 256 batches / 8 per cluster = 32 clusters = 128 CTAs
    ltc_main<<<BB / BPC * CLU, NTHR, SMEM_BYTES>>>(x, ts, gleak, vleak, cm,
                                                   ow, ob, hw, hb, out);
}